// round 6
// baseline (speedup 1.0000x reference)
#include <cuda_runtime.h>

// SSIM loss, vertical-first separable blur, FIELD-packed f32x2 end-to-end:
//   V: thread-per-column, rings (i1,i2) / (i1^2+i2^2, i1*i2) -> 22 FMA2/row,
//      results stored to smem as packed ulls (STS.64, no unpacking).
//   H: 2 cols/lane, conflict-free ull2 (LDS.128) window loads,
//      11 FMA2 per field-pair per pixel, dual accumulators, ZERO pack movs.
// Inputs: 2x [16,3,512,512] fp32. Output: 1 fp32 scalar.

typedef unsigned long long ull;
typedef ulonglong2 ull2;

#define NTHR    160
#define TILE_W  128
#define TILE_H  16
#define RAD     5
#define KW      11
#define VCOLS   (TILE_W + 2 * RAD)   // 138
#define VSTRIDE 140                  // ulls per row (16B aligned)
#define HH      512
#define WW      512
#define PLANES  48
#define GX      (WW / TILE_W)        // 4
#define GY      (HH / TILE_H)        // 32  (exact: no row masking)
#define NBLK    (GX * GY * PLANES)   // 6144

__device__ float        g_partials[NBLK];
__device__ unsigned int g_count = 0;

// Gaussian(sigma=1.5) 11 taps, normalized.
__device__ __forceinline__ constexpr float GW(int k) {
    return (k == 0 || k == 10) ? 0.00102838f
         : (k == 1 || k == 9)  ? 0.00759877f
         : (k == 2 || k == 8)  ? 0.03600075f
         : (k == 3 || k == 7)  ? 0.10936082f
         : (k == 4 || k == 6)  ? 0.21300554f
         :                       0.26601172f;
}

// ---- f32x2 helpers ----
__device__ __forceinline__ ull F2(float a, float b) {
    ull r; asm("mov.b64 %0,{%1,%2};" : "=l"(r) : "f"(a), "f"(b)); return r;
}
__device__ __forceinline__ void UF2(ull v, float& a, float& b) {
    asm("mov.b64 {%0,%1},%2;" : "=f"(a), "=f"(b) : "l"(v));
}
__device__ __forceinline__ ull FMA2(ull a, ull b, ull c) {
    ull r; asm("fma.rn.f32x2 %0,%1,%2,%3;" : "=l"(r) : "l"(a), "l"(b), "l"(c)); return r;
}

__global__ void __launch_bounds__(NTHR, 5)
ssim_main(const float* __restrict__ img1, const float* __restrict__ img2,
          float* __restrict__ out)
{
    // Packed field buffers: smA = (mu1,mu2), smQ = (qs,q12), per [row][col].
    __shared__ __align__(16) ull smA[TILE_H][VSTRIDE];
    __shared__ __align__(16) ull smQ[TILE_H][VSTRIDE];

    const int tid   = threadIdx.x;
    const int x0    = blockIdx.x * TILE_W;
    const int y0    = blockIdx.y * TILE_H;
    const int plane = blockIdx.z;
    const size_t pbase = (size_t)plane * (HH * WW);

    ull w2[6];
    #pragma unroll
    for (int k = 0; k < 6; ++k) w2[k] = F2(GW(k), GW(k));

    // ================= Vertical phase (field-packed f32x2) =================
    if (tid < VCOLS) {
        const int gx  = x0 + tid - RAD;
        const bool vx = ((unsigned)gx < WW);
        const int gxc = min(max(gx, 0), WW - 1);
        const float* __restrict__ p1 = img1 + pbase + gxc;
        const float* __restrict__ p2 = img2 + pbase + gxc;

        ull rab[KW];   // (i1, i2)
        ull rsp[KW];   // (i1^2+i2^2, i1*i2)
        float ca, cb;

        auto loadrow = [&](int i, float& a, float& b) {
            int gy = y0 + i - RAD;
            bool ok = vx && ((unsigned)gy < HH);
            int gyc = min(max(gy, 0), HH - 1);
            size_t off = (size_t)gyc * WW;
            a = ok ? __ldg(p1 + off) : 0.f;
            b = ok ? __ldg(p2 + off) : 0.f;
        };

        #pragma unroll
        for (int i = 0; i < KW - 1; ++i) {
            float a, b; loadrow(i, a, b);
            rab[i] = F2(a, b);
            rsp[i] = F2(fmaf(a, a, b * b), a * b);
        }
        loadrow(KW - 1, ca, cb);

        #pragma unroll
        for (int u = 0; u < TILE_H; ++u) {
            const int sl = (u + KW - 1) % KW;
            rab[sl] = F2(ca, cb);
            rsp[sl] = F2(fmaf(ca, ca, cb * cb), ca * cb);
            if (u < TILE_H - 1) loadrow(u + KW, ca, cb);

            // Dual accumulators to halve dependency-chain depth.
            ull ma = 0, mb = 0, qa = 0, qb = 0;
            #pragma unroll
            for (int j = 0; j < KW; ++j) {
                const int s = (u + j) % KW;            // compile-time
                const ull wj = w2[(j < 6) ? j : 10 - j];
                if (j & 1) { mb = FMA2(wj, rab[s], mb); qb = FMA2(wj, rsp[s], qb); }
                else       { ma = FMA2(wj, rab[s], ma); qa = FMA2(wj, rsp[s], qa); }
            }
            smA[u][tid] = FMA2(F2(1.f, 1.f), ma, mb);  // ma + mb (stays on fma pipe)
            smQ[u][tid] = FMA2(F2(1.f, 1.f), qa, qb);
        }
    }
    __syncthreads();

    // ================= Horizontal + SSIM (field-packed, no repacking) =====
    float acc = 0.f;
    if (tid < 128) {
        const int c2 = tid & 63;    // column pair: output cols 2c2, 2c2+1
        const int rs = tid >> 6;    // row slot (0 or 1)

        #pragma unroll 1
        for (int rr = 0; rr < 8; ++rr) {
            const int r = rr * 2 + rs;

            // 12-ull windows as 6 conflict-free LDS.128 each.
            ull2 wa[6], wq[6];
            {
                const ull2* __restrict__ pa = reinterpret_cast<const ull2*>(&smA[r][0]) + c2;
                const ull2* __restrict__ pq = reinterpret_cast<const ull2*>(&smQ[r][0]) + c2;
                #pragma unroll
                for (int j = 0; j < 6; ++j) { wa[j] = pa[j]; wq[j] = pq[j]; }
            }
            const ull* ha = reinterpret_cast<const ull*>(wa);  // ulls [2c2 .. 2c2+11]
            const ull* hq = reinterpret_cast<const ull*>(wq);

            #pragma unroll
            for (int d = 0; d < 2; ++d) {              // two output columns
                ull ma = 0, mb = 0, qa = 0, qb = 0;
                #pragma unroll
                for (int k = 0; k < KW; ++k) {
                    const ull wj = w2[(k < 6) ? k : 10 - k];
                    if (k & 1) { mb = FMA2(wj, ha[d + k], mb); qb = FMA2(wj, hq[d + k], qb); }
                    else       { ma = FMA2(wj, ha[d + k], ma); qa = FMA2(wj, hq[d + k], qa); }
                }
                ull mu = FMA2(F2(1.f, 1.f), ma, mb);
                ull qv = FMA2(F2(1.f, 1.f), qa, qb);

                float m1, m2, qs, q12;
                UF2(mu, m1, m2);
                UF2(qv, qs, q12);

                float mu12 = m1 * m2;
                float mu1s = m1 * m1;
                float mu2s = m2 * m2;
                float s12  = q12 - mu12;
                float n1   = fmaf(2.f, mu12, 1e-4f);
                float n2   = fmaf(2.f, s12,  9e-4f);
                float ttv  = mu1s + mu2s;
                float d1   = ttv + 1e-4f;
                float d2   = (qs - ttv) + 9e-4f;
                acc += __fdividef(n1 * n2, d1 * d2);
            }
        }
    }

    // ================= Reduction =================
    #pragma unroll
    for (int o = 16; o; o >>= 1)
        acc += __shfl_xor_sync(0xFFFFFFFFu, acc, o);

    __shared__ float ws[NTHR / 32];
    if ((tid & 31) == 0) ws[tid >> 5] = acc;
    __syncthreads();

    const int bid = (blockIdx.z * GY + blockIdx.y) * GX + blockIdx.x;
    __shared__ unsigned int is_last;
    if (tid == 0) {
        float bs = 0.f;
        #pragma unroll
        for (int i = 0; i < NTHR / 32; ++i) bs += ws[i];
        __stcg(&g_partials[bid], bs);
        __threadfence();
        is_last = (atomicAdd(&g_count, 1u) == (unsigned)(NBLK - 1));
    }
    __syncthreads();

    if (is_last) {
        double s = 0.0;
        for (int i = tid; i < NBLK; i += NTHR)
            s += (double)__ldcg(&g_partials[i]);
        #pragma unroll
        for (int o = 16; o; o >>= 1)
            s += __shfl_xor_sync(0xFFFFFFFFu, s, o);
        __shared__ double wd[NTHR / 32];
        if ((tid & 31) == 0) wd[tid >> 5] = s;
        __syncthreads();
        if (tid == 0) {
            double bs = 0.0;
            #pragma unroll
            for (int i = 0; i < NTHR / 32; ++i) bs += wd[i];
            double n = (double)PLANES * HH * WW;
            out[0] = (float)(1.0 - bs / n);
            g_count = 0;   // reset for next graph replay
        }
    }
}

extern "C" void kernel_launch(void* const* d_in, const int* in_sizes, int n_in,
                              void* d_out, int out_size)
{
    (void)in_sizes; (void)n_in; (void)out_size;
    const float* img1 = (const float*)d_in[0];
    const float* img2 = (const float*)d_in[1];
    float* out = (float*)d_out;

    dim3 grid(GX, GY, PLANES);
    ssim_main<<<grid, NTHR>>>(img1, img2, out);
}

// round 7
// speedup vs baseline: 1.0372x; 1.0372x over previous
#include <cuda_runtime.h>

// SSIM loss, vertical-first separable blur, field-packed f32x2 end-to-end:
//   V: thread-per-column, packed rings (i1,i2)/(i1^2+i2^2, i1*i2), 22 FMA2/row,
//      stores packed ulls (STS.64).
//   H: 4 px/thread/row from ONE 14-ull window per field array (7 LDS.128 each),
//      11 FMA2 per field-pair per px, zero pack movs, 8 indep chains per iter.
// Inputs: 2x [16,3,512,512] fp32. Output: 1 fp32 scalar.

typedef unsigned long long ull;
typedef ulonglong2 ull2;

#define NTHR    160
#define TILE_W  128
#define TILE_H  16
#define RAD     5
#define KW      11
#define VCOLS   (TILE_W + 2 * RAD)   // 138
#define VSTRIDE 140                  // ulls per row (1120B, 16B aligned)
#define HH      512
#define WW      512
#define PLANES  48
#define GX      (WW / TILE_W)        // 4
#define GY      (HH / TILE_H)        // 32
#define NBLK    (GX * GY * PLANES)   // 6144

__device__ float        g_partials[NBLK];
__device__ unsigned int g_count = 0;

// Gaussian(sigma=1.5) 11 taps, normalized.
__device__ __forceinline__ constexpr float GW(int k) {
    return (k == 0 || k == 10) ? 0.00102838f
         : (k == 1 || k == 9)  ? 0.00759877f
         : (k == 2 || k == 8)  ? 0.03600075f
         : (k == 3 || k == 7)  ? 0.10936082f
         : (k == 4 || k == 6)  ? 0.21300554f
         :                       0.26601172f;
}

// ---- f32x2 helpers ----
__device__ __forceinline__ ull F2(float a, float b) {
    ull r; asm("mov.b64 %0,{%1,%2};" : "=l"(r) : "f"(a), "f"(b)); return r;
}
__device__ __forceinline__ void UF2(ull v, float& a, float& b) {
    asm("mov.b64 {%0,%1},%2;" : "=f"(a), "=f"(b) : "l"(v));
}
__device__ __forceinline__ ull FMA2(ull a, ull b, ull c) {
    ull r; asm("fma.rn.f32x2 %0,%1,%2,%3;" : "=l"(r) : "l"(a), "l"(b), "l"(c)); return r;
}

__global__ void __launch_bounds__(NTHR, 4)
ssim_main(const float* __restrict__ img1, const float* __restrict__ img2,
          float* __restrict__ out)
{
    // Packed field buffers: smA = (mu1,mu2), smQ = (qs,q12) per [row][col].
    __shared__ __align__(16) ull smA[TILE_H][VSTRIDE];
    __shared__ __align__(16) ull smQ[TILE_H][VSTRIDE];

    const int tid   = threadIdx.x;
    const int x0    = blockIdx.x * TILE_W;
    const int y0    = blockIdx.y * TILE_H;
    const int plane = blockIdx.z;
    const size_t pbase = (size_t)plane * (HH * WW);

    ull w2[6];
    #pragma unroll
    for (int k = 0; k < 6; ++k) w2[k] = F2(GW(k), GW(k));
    const ull ONE2 = F2(1.f, 1.f);

    // ================= Vertical phase (field-packed f32x2) =================
    if (tid < VCOLS) {
        const int gx  = x0 + tid - RAD;
        const bool vx = ((unsigned)gx < WW);
        const int gxc = min(max(gx, 0), WW - 1);
        const float* __restrict__ p1 = img1 + pbase + gxc;
        const float* __restrict__ p2 = img2 + pbase + gxc;

        ull rab[KW];   // (i1, i2)
        ull rsp[KW];   // (i1^2+i2^2, i1*i2)
        float ca, cb;

        auto loadrow = [&](int i, float& a, float& b) {
            int gy = y0 + i - RAD;
            bool ok = vx && ((unsigned)gy < HH);
            int gyc = min(max(gy, 0), HH - 1);
            size_t off = (size_t)gyc * WW;
            a = ok ? __ldg(p1 + off) : 0.f;
            b = ok ? __ldg(p2 + off) : 0.f;
        };

        #pragma unroll
        for (int i = 0; i < KW - 1; ++i) {
            float a, b; loadrow(i, a, b);
            rab[i] = F2(a, b);
            rsp[i] = F2(fmaf(a, a, b * b), a * b);
        }
        loadrow(KW - 1, ca, cb);

        #pragma unroll
        for (int u = 0; u < TILE_H; ++u) {
            const int sl = (u + KW - 1) % KW;
            rab[sl] = F2(ca, cb);
            rsp[sl] = F2(fmaf(ca, ca, cb * cb), ca * cb);
            if (u < TILE_H - 1) loadrow(u + KW, ca, cb);

            ull ma = 0, mb = 0, qa = 0, qb = 0;   // dual chains
            #pragma unroll
            for (int j = 0; j < KW; ++j) {
                const int s = (u + j) % KW;            // compile-time
                const ull wj = w2[(j < 6) ? j : 10 - j];
                if (j & 1) { mb = FMA2(wj, rab[s], mb); qb = FMA2(wj, rsp[s], qb); }
                else       { ma = FMA2(wj, rab[s], ma); qa = FMA2(wj, rsp[s], qa); }
            }
            smA[u][tid] = FMA2(ONE2, ma, mb);
            smQ[u][tid] = FMA2(ONE2, qa, qb);
        }
    }
    __syncthreads();

    // ========= Horizontal + SSIM: 4 px/thread/row, one shared window =======
    float acc = 0.f;
    if (tid < 128) {
        const int cg = tid & 31;    // output cols 4cg .. 4cg+3
        const int rg = tid >> 5;    // row slot (0..3)

        #pragma unroll 1
        for (int rr = 0; rr < 4; ++rr) {
            const int r = rr * 4 + rg;

            // 14-ull windows (cols 4cg..4cg+13) as 7 LDS.128 per field array.
            ull2 wa[7], wq[7];
            {
                const ull2* __restrict__ pa =
                    reinterpret_cast<const ull2*>(&smA[r][0]) + 2 * cg;
                const ull2* __restrict__ pq =
                    reinterpret_cast<const ull2*>(&smQ[r][0]) + 2 * cg;
                #pragma unroll
                for (int j = 0; j < 7; ++j) { wa[j] = pa[j]; wq[j] = pq[j]; }
            }
            const ull* ha = reinterpret_cast<const ull*>(wa);
            const ull* hq = reinterpret_cast<const ull*>(wq);

            #pragma unroll
            for (int d = 0; d < 4; ++d) {          // four output columns
                ull ma = 0, mb = 0, qa = 0, qb = 0;
                #pragma unroll
                for (int k = 0; k < KW; ++k) {
                    const ull wj = w2[(k < 6) ? k : 10 - k];
                    if (k & 1) { mb = FMA2(wj, ha[d + k], mb); qb = FMA2(wj, hq[d + k], qb); }
                    else       { ma = FMA2(wj, ha[d + k], ma); qa = FMA2(wj, hq[d + k], qa); }
                }
                ull mu = FMA2(ONE2, ma, mb);
                ull qv = FMA2(ONE2, qa, qb);

                float m1, m2, qs, q12;
                UF2(mu, m1, m2);
                UF2(qv, qs, q12);

                float mu12 = m1 * m2;
                float mu1s = m1 * m1;
                float mu2s = m2 * m2;
                float s12  = q12 - mu12;
                float n1   = fmaf(2.f, mu12, 1e-4f);
                float n2   = fmaf(2.f, s12,  9e-4f);
                float ttv  = mu1s + mu2s;
                float d1   = ttv + 1e-4f;
                float d2   = (qs - ttv) + 9e-4f;
                acc += __fdividef(n1 * n2, d1 * d2);
            }
        }
    }

    // ================= Reduction =================
    #pragma unroll
    for (int o = 16; o; o >>= 1)
        acc += __shfl_xor_sync(0xFFFFFFFFu, acc, o);

    __shared__ float ws[NTHR / 32];
    if ((tid & 31) == 0) ws[tid >> 5] = acc;
    __syncthreads();

    const int bid = (blockIdx.z * GY + blockIdx.y) * GX + blockIdx.x;
    __shared__ unsigned int is_last;
    if (tid == 0) {
        float bs = 0.f;
        #pragma unroll
        for (int i = 0; i < NTHR / 32; ++i) bs += ws[i];
        __stcg(&g_partials[bid], bs);
        __threadfence();
        is_last = (atomicAdd(&g_count, 1u) == (unsigned)(NBLK - 1));
    }
    __syncthreads();

    if (is_last) {
        double s = 0.0;
        for (int i = tid; i < NBLK; i += NTHR)
            s += (double)__ldcg(&g_partials[i]);
        #pragma unroll
        for (int o = 16; o; o >>= 1)
            s += __shfl_xor_sync(0xFFFFFFFFu, s, o);
        __shared__ double wd[NTHR / 32];
        if ((tid & 31) == 0) wd[tid >> 5] = s;
        __syncthreads();
        if (tid == 0) {
            double bs = 0.0;
            #pragma unroll
            for (int i = 0; i < NTHR / 32; ++i) bs += wd[i];
            double n = (double)PLANES * HH * WW;
            out[0] = (float)(1.0 - bs / n);
            g_count = 0;   // reset for next graph replay
        }
    }
}

extern "C" void kernel_launch(void* const* d_in, const int* in_sizes, int n_in,
                              void* d_out, int out_size)
{
    (void)in_sizes; (void)n_in; (void)out_size;
    const float* img1 = (const float*)d_in[0];
    const float* img2 = (const float*)d_in[1];
    float* out = (float*)d_out;

    dim3 grid(GX, GY, PLANES);
    ssim_main<<<grid, NTHR>>>(img1, img2, out);
}